// round 16
// baseline (speedup 1.0000x reference)
#include <cuda_runtime.h>
#include <cstdint>
#include <cstddef>

// ---------------------------------------------------------------------------
// BlocDiagLinear: out[b, n*128+r] = sum_c x[b, n*128+c] * blocks[n, r, c]
// 64 GEMMs (M=4096, N=128, K=128) fp32 -> mma.sync.m16n8k8.tf32, fp32 accum.
//
// R16 = R10 (best skeleton: grid (64,32), CTA 128x128x128, 8 warps 4Mx2N,
// 3-stage cp.async ring, XOR-swizzled smem, ldmatrix.x4, raw-fp32->tf32 mma)
// with a STRICTLY TIGHTER SCHEDULE:
//   per chunk q:  wait_group 1 ; __syncthreads ; issue chunk q+2 ; compute q
// The pre-compute barrier already proves all warps finished compute q-1, so
// refilling buffer (q-1)%3 (= the buffer chunk q+2 needs) right after it is
// safe. This removes the post-compute barrier (8 -> 4 barriers per tile) and
// starts each refill a full compute-phase earlier (DRAM fed during compute).
// ---------------------------------------------------------------------------

static constexpr int THREADS = 256;
static constexpr int STAGE_BYTES = 32768;            // A 16KB + B 16KB
static constexpr int SMEM_BYTES  = 3 * STAGE_BYTES;  // 98304 -> 2 CTAs/SM

__device__ __forceinline__ uint32_t smem_u32(const void* p) {
    uint32_t a;
    asm("{ .reg .u64 t; cvta.to.shared.u64 t, %1; cvt.u32.u64 %0, t; }"
        : "=r"(a) : "l"(p));
    return a;
}

// Issue one K=32 chunk (A: x tile, B: blocks[n]) via cp.async.
__device__ __forceinline__ void issue_stage(uint32_t sbase,
                                            const float* __restrict__ xg,
                                            const float* __restrict__ bg,
                                            int s)
{
    #pragma unroll
    for (int it = 0; it < 4; it++) {
        const int j   = threadIdx.x + it * 256;   // 0..1023 int4 atoms
        const int row = j >> 3;                   // 0..127
        const int c   = j & 7;                    // 16B atom within 128B row
        const uint32_t sw = (uint32_t)((c ^ (row & 7)) << 4);
        const uint32_t dA = sbase + row * 128 + sw;
        const float* sA = xg + (size_t)row * 8192 + s * 32 + c * 4;
        asm volatile("cp.async.cg.shared.global [%0], [%1], 16;"
                     :: "r"(dA), "l"(sA));
        const uint32_t dB = sbase + 16384 + row * 128 + sw;
        const float* sB = bg + row * 128 + s * 32 + c * 4;
        asm volatile("cp.async.cg.shared.global [%0], [%1], 16;"
                     :: "r"(dB), "l"(sB));
    }
    asm volatile("cp.async.commit_group;" ::: "memory");
}

// Compute one K=32 chunk (4 k-steps of m16n8k8). Raw fp32 fragments feed the
// tf32 mma directly; HW truncation handles the tf32 conversion. (== R10)
__device__ __forceinline__ void compute_stage(uint32_t abase, uint32_t bbase,
                                              int mrow, int ncol, int lane,
                                              float acc[2][8][4])
{
    const int t4 = lane >> 3;     // tile index within ldmatrix.x4
    const int tr = lane & 7;      // row within tile

    #pragma unroll
    for (int kk = 0; kk < 4; kk++) {
        uint32_t a[2][4];
        #pragma unroll
        for (int i = 0; i < 2; i++) {
            const int r = mrow + 16 * i + ((t4 & 1) << 3) + tr;
            const int c = 2 * kk + (t4 >> 1);
            const uint32_t addr = abase + r * 128 + ((uint32_t)(c ^ (r & 7)) << 4);
            asm volatile(
                "ldmatrix.sync.aligned.m8n8.x4.shared.b16 {%0,%1,%2,%3}, [%4];"
                : "=r"(a[i][0]), "=r"(a[i][1]), "=r"(a[i][2]), "=r"(a[i][3])
                : "r"(addr));
        }

        uint32_t b[8][2];
        #pragma unroll
        for (int p = 0; p < 4; p++) {
            const int rn = ncol + (2 * p + (t4 >> 1)) * 8 + tr;
            const int c  = 2 * kk + (t4 & 1);
            const uint32_t addr = bbase + rn * 128 + ((uint32_t)(c ^ (rn & 7)) << 4);
            asm volatile(
                "ldmatrix.sync.aligned.m8n8.x4.shared.b16 {%0,%1,%2,%3}, [%4];"
                : "=r"(b[2 * p][0]), "=r"(b[2 * p][1]),
                  "=r"(b[2 * p + 1][0]), "=r"(b[2 * p + 1][1])
                : "r"(addr));
        }

        #pragma unroll
        for (int jj = 0; jj < 8; jj++)
            #pragma unroll
            for (int i = 0; i < 2; i++) {
                asm volatile(
                    "mma.sync.aligned.m16n8k8.row.col.f32.tf32.tf32.f32 "
                    "{%0,%1,%2,%3}, {%4,%5,%6,%7}, {%8,%9}, {%0,%1,%2,%3};"
                    : "+f"(acc[i][jj][0]), "+f"(acc[i][jj][1]),
                      "+f"(acc[i][jj][2]), "+f"(acc[i][jj][3])
                    : "r"(a[i][0]), "r"(a[i][1]), "r"(a[i][2]), "r"(a[i][3]),
                      "r"(b[jj][0]), "r"(b[jj][1]));
            }
    }
}

__global__ void __launch_bounds__(THREADS, 2)
bdl_mma_kernel(const float* __restrict__ x,
               const float* __restrict__ blocks,
               float* __restrict__ out)
{
    extern __shared__ char smem[];
    const uint32_t sb = smem_u32(smem);
    const uint32_t B0 = sb;
    const uint32_t B1 = sb + STAGE_BYTES;
    const uint32_t B2 = sb + 2 * STAGE_BYTES;

    const int tid  = threadIdx.x;
    const int wid  = tid >> 5;
    const int lane = tid & 31;
    const int g    = lane >> 2;
    const int tig  = lane & 3;

    const int n  = blockIdx.x;
    const int m0 = blockIdx.y * 128;

    const int mrow = (wid >> 1) * 32;
    const int ncol = (wid & 1) * 64;

    const float* xg = x + (size_t)m0 * 8192 + n * 128;
    const float* bg = blocks + (size_t)n * 16384;

    float acc[2][8][4];
    #pragma unroll
    for (int i = 0; i < 2; i++)
        #pragma unroll
        for (int j = 0; j < 8; j++)
            #pragma unroll
            for (int v = 0; v < 4; v++)
                acc[i][j][v] = 0.0f;

    // ---- prologue: chunks 0,1 in flight ----
    issue_stage(B0, xg, bg, 0);
    issue_stage(B1, xg, bg, 1);

    // ---- chunk 0: wait c0; barrier; issue c2; compute c0 ----
    asm volatile("cp.async.wait_group 1;" ::: "memory");
    __syncthreads();
    issue_stage(B2, xg, bg, 2);
    compute_stage(B0, B0 + 16384, mrow, ncol, lane, acc);

    // ---- chunk 1: wait c1; barrier (proves all warps done c0 -> B0 free);
    //      issue c3 -> B0; compute c1 ----
    asm volatile("cp.async.wait_group 1;" ::: "memory");
    __syncthreads();
    issue_stage(B0, xg, bg, 3);
    compute_stage(B1, B1 + 16384, mrow, ncol, lane, acc);

    // ---- chunk 2: wait c2 (pending {c3} <= 1); barrier; compute c2 ----
    asm volatile("cp.async.wait_group 1;" ::: "memory");
    __syncthreads();
    compute_stage(B2, B2 + 16384, mrow, ncol, lane, acc);

    // ---- chunk 3: wait c3; barrier; compute c3 ----
    asm volatile("cp.async.wait_group 0;" ::: "memory");
    __syncthreads();
    compute_stage(B0, B0 + 16384, mrow, ncol, lane, acc);

    // ---- epilogue: float2 stores (each quad fills a full 32B sector) ----
    float* obase = out + (size_t)m0 * 8192 + n * 128;
    #pragma unroll
    for (int i = 0; i < 2; i++) {
        const int r0 = mrow + 16 * i + g;
        #pragma unroll
        for (int jj = 0; jj < 8; jj++) {
            const int c = ncol + 8 * jj + 2 * tig;
            *reinterpret_cast<float2*>(obase + (size_t)r0 * 8192 + c) =
                make_float2(acc[i][jj][0], acc[i][jj][1]);
            *reinterpret_cast<float2*>(obase + (size_t)(r0 + 8) * 8192 + c) =
                make_float2(acc[i][jj][2], acc[i][jj][3]);
        }
    }
}

extern "C" void kernel_launch(void* const* d_in, const int* in_sizes, int n_in,
                              void* d_out, int out_size)
{
    (void)in_sizes; (void)n_in; (void)out_size;
    const float* x      = (const float*)d_in[0];   // [4096, 8192]
    const float* blocks = (const float*)d_in[1];   // [64, 128, 128]
    float* out          = (float*)d_out;           // [4096, 8192]

    cudaFuncSetAttribute(bdl_mma_kernel,
                         cudaFuncAttributeMaxDynamicSharedMemorySize, SMEM_BYTES);
    dim3 grid(64, 32, 1);
    bdl_mma_kernel<<<grid, THREADS, SMEM_BYTES>>>(x, blocks, out);
}